// round 15
// baseline (speedup 1.0000x reference)
#include <cuda_runtime.h>

// VolumeRenderingNeuS — bit-faithful JAX/XLA:CPU emulation (ReduceWindowRewriter
// cumsum B=16, Cephes exp/log, strict RN) — 6-launch schedule:
//   K1 ew_fused     : elementwise alpha/logx (float2) + I1 + I2 + A2
//   K2 seg          : scatter searchsorted(ray_ids) -> seg_start
//   K3 up3          : A2 (31250) -> I3 + A3 (1954)
//   K4 midscan+down3: scan A3 in one block -> S4; apply offsets to I3 -> S3
//   K5 down2        : I2[j] = fl(S3[j/16-1] + I2[j]) -> S2 (500k, in place)
//   K6 final        : warp-per-ray; c = fl(fl(S2[t1-1]+I1[i]) - logx[i]);
//                     weights + per-ray rgb sums
// Every fl() op composes identically to the R10 passing kernel.

#define MAXN 8000000
#define MAXR ((1 << 18) + 2)
#define PAD(j) ((j) + ((j) >> 4))

__device__ float2 g_alx[MAXN];    // (alpha, logx) packed
__device__ float  g_I1[MAXN];
__device__ float  g_small[1200000];
__device__ int    g_seg[MAXR];

// ---- XLA:CPU Cephes/Eigen exp (no FMA) ----
__device__ __forceinline__ float cephes_expf(float input) {
    const float exp_hi = 88.3762626647950f;
    const float exp_lo = -88.3762626647949f;
    const float log2e  = 1.44269504088896341f;
    float xc = fminf(fmaxf(input, exp_lo), exp_hi);
    float fx = floorf(__fadd_rn(__fmul_rn(xc, log2e), 0.5f));
    float x = __fsub_rn(xc, __fmul_rn(0.693359375f, fx));
    x = __fsub_rn(x, __fmul_rn(-2.12194440e-4f, fx));
    float z = __fmul_rn(x, x);
    float y = __fadd_rn(__fmul_rn(x, 1.9875691500e-4f), 1.3981999507e-3f);
    y = __fadd_rn(__fmul_rn(y, x), 8.3334519073e-3f);
    y = __fadd_rn(__fmul_rn(y, x), 4.1665795894e-2f);
    y = __fadd_rn(__fmul_rn(y, x), 1.6666665459e-1f);
    y = __fadd_rn(__fmul_rn(y, x), 5.0000001201e-1f);
    y = __fadd_rn(__fmul_rn(y, z), x);
    y = __fadd_rn(1.0f, y);
    int n = (int)fx;
    return __fmul_rn(y, __int_as_float((n + 0x7f) << 23));
}

// ---- XLA:CPU Cephes/Eigen log (no FMA) ----
__device__ __forceinline__ float cephes_logf(float input) {
    const float sqrt_half = 0.707106781186547524f;
    int ix = __float_as_int(input);
    int emm0 = (int)(((unsigned)ix) >> 23) - 0x7e;
    float e = (float)emm0;
    float m = __int_as_float((ix & 0x807fffff) | 0x3f000000);
    bool mask = (m < sqrt_half);
    float tmp = mask ? m : 0.0f;
    float x = __fsub_rn(m, 1.0f);
    e = __fsub_rn(e, mask ? 1.0f : 0.0f);
    x = __fadd_rn(x, tmp);
    float z = __fmul_rn(x, x);
    float y = __fadd_rn(__fmul_rn(x, 7.0376836292e-2f), -1.1514610310e-1f);
    y = __fadd_rn(__fmul_rn(y, x), 1.1676998740e-1f);
    y = __fadd_rn(__fmul_rn(y, x), -1.2420140846e-1f);
    y = __fadd_rn(__fmul_rn(y, x), 1.4249322787e-1f);
    y = __fadd_rn(__fmul_rn(y, x), -1.6668057665e-1f);
    y = __fadd_rn(__fmul_rn(y, x), 2.0000714765e-1f);
    y = __fadd_rn(__fmul_rn(y, x), -2.4999993993e-1f);
    y = __fadd_rn(__fmul_rn(y, x), 3.3333331174e-1f);
    y = __fmul_rn(y, x);
    y = __fmul_rn(y, z);
    y = __fadd_rn(__fmul_rn(e, -2.12194440e-4f), y);
    y = __fsub_rn(y, __fmul_rn(0.5f, z));
    x = __fadd_rn(x, y);
    x = __fadd_rn(__fmul_rn(e, 0.693359375f), x);
    return x;
}

__device__ __forceinline__ float xla_sigmoid(float x) {
    return __fdiv_rn(1.0f, __fadd_rn(1.0f, cephes_expf(-x)));
}

// ---- K1: elementwise + level-1 scans (I1) + level-2 scans (I2,A2) ----
__global__ void __launch_bounds__(256)
ew_fused_kernel(const float* __restrict__ sdf, const float* __restrict__ grad,
                const float* __restrict__ dirs, const float* __restrict__ dt,
                const float* __restrict__ ca_p, const float* __restrict__ beta_p,
                float2* __restrict__ alx_out, float* __restrict__ I1,
                float* __restrict__ I2, float* __restrict__ A2,
                int N, int T1, int T2)
{
    __shared__ float sm[4352];
    __shared__ float smA[256];
    __shared__ float smI2[256];
    const int base = blockIdx.x * 4096;
    const float ca = ca_p[0];
    const float beta = beta_p[0];
    const float omca = __fsub_rn(1.0f, ca);

    #pragma unroll 1
    for (int k = 0; k < 16; k++) {
        int j = k * 256 + threadIdx.x;
        int i = base + j;
        float lx = 0.0f;
        if (i < N) {
            float m0 = __fmul_rn(dirs[3*i+0], grad[3*i+0]);
            float m1 = __fmul_rn(dirs[3*i+1], grad[3*i+1]);
            float m2 = __fmul_rn(dirs[3*i+2], grad[3*i+2]);
            float tc = __fadd_rn(__fadd_rn(m0, m1), m2);
            float ntc = -tc;
            float A = fmaxf(__fadd_rn(__fmul_rn(ntc, 0.5f), 0.5f), 0.0f);
            float Bv = fmaxf(ntc, 0.0f);
            float ic_pos = __fadd_rn(__fmul_rn(A, omca), __fmul_rn(Bv, ca));
            float m = __fmul_rn(ic_pos, dt[i]);
            float h = __fmul_rn(m, 0.5f);
            float s = sdf[i];
            float en = __fsub_rn(s, h);
            float ep = __fadd_rn(s, h);
            float pc = xla_sigmoid(__fmul_rn(ep, beta));
            float nc = xla_sigmoid(__fmul_rn(en, beta));
            float num = __fadd_rn(__fsub_rn(pc, nc), 1e-6f);
            float den = __fadd_rn(pc, 1e-6f);
            float a = fminf(fmaxf(__fdiv_rn(num, den), 0.0f), 1.0f);
            float om = __fadd_rn(__fsub_rn(1.0f, a), 1e-6f);
            lx = cephes_logf(om);
            alx_out[i] = make_float2(a, lx);
        }
        sm[PAD(j)] = lx;
    }
    __syncthreads();

    const int tg = blockIdx.x * 256 + threadIdx.x;   // global level-1 tile id
    {
        float a1 = 0.0f;
        if (tg < T1) {
            float acc = 0.0f;
            int jb = threadIdx.x * 16;
            #pragma unroll
            for (int c = 0; c < 16; c++) {
                int p = PAD(jb + c);
                acc = __fadd_rn(acc, sm[p]);
                sm[p] = acc;
            }
            a1 = acc;
        }
        smA[threadIdx.x] = a1;
    }
    __syncthreads();

    #pragma unroll 1
    for (int k = 0; k < 16; k++) {
        int j = k * 256 + threadIdx.x;
        int i = base + j;
        if (i < N) I1[i] = sm[PAD(j)];
    }

    if (threadIdx.x < 16) {
        int t2g = blockIdx.x * 16 + threadIdx.x;
        if (t2g < T2) {
            float acc = 0.0f;
            int jb = threadIdx.x * 16;
            #pragma unroll
            for (int c = 0; c < 16; c++) {
                acc = __fadd_rn(acc, smA[jb + c]);
                smI2[jb + c] = acc;
            }
            A2[t2g] = acc;
        }
    }
    __syncthreads();
    if (tg < T1) I2[tg] = smI2[threadIdx.x];
}

// ---- K2: scatter searchsorted -> seg_start ----
__global__ void __launch_bounds__(256)
seg_kernel(const int* __restrict__ ray_ids, int N, int n_rays,
           int* __restrict__ seg)
{
    int i = blockIdx.x * blockDim.x + threadIdx.x;
    if (i >= N) return;
    int cur = ray_ids[i];
    int prev = (i == 0) ? -1 : ray_ids[i - 1];
    for (int r = prev + 1; r <= cur; r++) seg[r] = i;
    if (i == N - 1)
        for (int r = cur + 1; r <= n_rays; r++) seg[r] = N;
}

// ---- K3: up level 3 (A2 -> I3, A3), smem-staged coalesced ----
__global__ void __launch_bounds__(256)
up_smem_kernel(const float* __restrict__ src, int n, int ntiles,
               float* __restrict__ inner, float* __restrict__ sums)
{
    __shared__ float sm[4352];
    const int base = blockIdx.x * 4096;
    #pragma unroll
    for (int k = 0; k < 16; k++) {
        int j = k * 256 + threadIdx.x;
        int g = base + j;
        sm[PAD(j)] = (g < n) ? src[g] : 0.0f;   // zero padding
    }
    __syncthreads();
    {
        int tg = blockIdx.x * 256 + threadIdx.x;
        if (tg < ntiles) {
            float acc = 0.0f;
            int jb = threadIdx.x * 16;
            #pragma unroll
            for (int c = 0; c < 16; c++) {
                int p = PAD(jb + c);
                acc = __fadd_rn(acc, sm[p]);
                sm[p] = acc;
            }
            sums[tg] = acc;
        }
    }
    __syncthreads();
    #pragma unroll
    for (int k = 0; k < 16; k++) {
        int j = k * 256 + threadIdx.x;
        int g = base + j;
        if (g < n) inner[g] = sm[PAD(j)];
    }
}

// ---- K4: scan A3 (1954) in one block -> S4, then apply offsets to I3 ----
__global__ void __launch_bounds__(256)
midscan_down3_kernel(float* __restrict__ x, int n,
                     float* __restrict__ I3, int nI3)
{
    __shared__ float sm[4400];
    int m[8], off[8];
    int L = 0; m[0] = n; off[0] = 0;
    while (m[L] > 16) {
        m[L+1] = (m[L] + 15) / 16;
        off[L+1] = off[L] + m[L];
        L++;
    }
    for (int i = threadIdx.x; i < n; i += blockDim.x) sm[i] = x[i];
    __syncthreads();

    for (int l = 0; l < L; l++) {
        for (int t = threadIdx.x; t < m[l+1]; t += blockDim.x) {
            float acc = 0.0f;
            int b = off[l] + t * 16;
            for (int c = 0; c < 16; c++) {
                int j = t * 16 + c;
                float v = (j < m[l]) ? sm[b + c] : 0.0f;
                acc = __fadd_rn(acc, v);
                if (j < m[l]) sm[b + c] = acc;
            }
            sm[off[l+1] + t] = acc;
        }
        __syncthreads();
    }
    if (threadIdx.x == 0) {
        float acc = 0.0f;
        for (int i = 0; i < m[L]; i++) {
            acc = __fadd_rn(acc, sm[off[L] + i]);
            sm[off[L] + i] = acc;
        }
    }
    __syncthreads();
    for (int l = L - 1; l >= 0; l--) {
        for (int t = threadIdx.x; t < m[l+1]; t += blockDim.x) {
            if (t == 0) continue;
            float o = sm[off[l+1] + t - 1];
            int b = off[l] + t * 16;
            for (int c = 0; c < 16; c++) {
                int j = t * 16 + c;
                if (j < m[l]) sm[b + c] = __fadd_rn(o, sm[b + c]);
            }
        }
        __syncthreads();
    }
    for (int i = threadIdx.x; i < n; i += blockDim.x) x[i] = sm[i];
    // down3: I3[j] += S4[j/16 - 1]   (S4 = sm[0..n), scanned A3)
    for (int j = threadIdx.x; j < nI3; j += blockDim.x) {
        int t = j >> 4;
        if (t) I3[j] = __fadd_rn(sm[t - 1], I3[j]);
    }
}

// ---- K5: down2 — I2[j] = fl(S3[j/16-1] + I2[j])  (in place -> S2) ----
__global__ void __launch_bounds__(256)
down2_kernel(const float* __restrict__ S3, float* __restrict__ I2, int n)
{
    int j = blockIdx.x * blockDim.x + threadIdx.x;
    if (j >= n) return;
    int t = j >> 4;
    if (t == 0) return;
    I2[j] = __fadd_rn(S3[t - 1], I2[j]);
}

// ---- K6: warp-per-ray weights + rgb segment sums (2-load cexcl) ----
__global__ void __launch_bounds__(256)
final_kernel(const float2* __restrict__ alx, const float* __restrict__ I1,
             const float* __restrict__ S2, const float* __restrict__ rgb,
             const int* __restrict__ seg,
             float* __restrict__ rgb_out, float* __restrict__ w_out,
             int N, int n_rays)
{
    const int r = (blockIdx.x * (blockDim.x >> 5)) + (threadIdx.x >> 5);
    const int lane = threadIdx.x & 31;
    if (r >= n_rays) return;

    const int start = seg[r];
    const int end   = seg[r + 1];

    float base = 0.0f;
    if (start < end) {
        float2 al0 = alx[start];
        int t = start >> 4;
        float s = I1[start];
        if (t) s = __fadd_rn(S2[t - 1], s);
        base = __fsub_rn(s, al0.y);
    }

    float ax = 0.0f, ay = 0.0f, az = 0.0f;
    for (int i = start + lane; i < end; i += 32) {
        float2 al = alx[i];
        int t = i >> 4;
        float s = I1[i];
        if (t) s = __fadd_rn(S2[t - 1], s);
        float c = __fsub_rn(s, al.y);
        float T = cephes_expf(__fsub_rn(c, base));
        float w = __fmul_rn(al.x, T);
        w_out[i] = w;
        ax = __fadd_rn(ax, __fmul_rn(w, rgb[3*i+0]));
        ay = __fadd_rn(ay, __fmul_rn(w, rgb[3*i+1]));
        az = __fadd_rn(az, __fmul_rn(w, rgb[3*i+2]));
    }
    #pragma unroll
    for (int o = 16; o; o >>= 1) {
        ax = __fadd_rn(ax, __shfl_xor_sync(0xffffffffu, ax, o));
        ay = __fadd_rn(ay, __shfl_xor_sync(0xffffffffu, ay, o));
        az = __fadd_rn(az, __shfl_xor_sync(0xffffffffu, az, o));
    }
    if (lane == 0) {
        rgb_out[3*r+0] = ax;
        rgb_out[3*r+1] = ay;
        rgb_out[3*r+2] = az;
    }
}

extern "C" void kernel_launch(void* const* d_in, const int* in_sizes, int n_in,
                              void* d_out, int out_size)
{
    const float* sdf     = (const float*)d_in[0];
    const float* grad    = (const float*)d_in[1];
    const float* dirs    = (const float*)d_in[2];
    const float* dt      = (const float*)d_in[3];
    const float* rgb     = (const float*)d_in[4];
    const float* ca      = (const float*)d_in[5];
    const float* beta    = (const float*)d_in[6];
    const int*   ray_ids = (const int*)d_in[7];

    const int N      = in_sizes[0];
    const int n_rays = (out_size - N) / 3;
    float* out     = (float*)d_out;
    float* rgb_out = out;
    float* w_out   = out + 3 * n_rays;

    float2* palx;
    float *pI1, *psm;
    int *pseg;
    cudaGetSymbolAddress((void**)&palx, g_alx);
    cudaGetSymbolAddress((void**)&pI1,  g_I1);
    cudaGetSymbolAddress((void**)&psm,  g_small);
    cudaGetSymbolAddress((void**)&pseg, g_seg);

    const int T1 = (N + 15) / 16;       // 500000
    const int T2 = (T1 + 15) / 16;      // 31250
    const int T3 = (T2 + 15) / 16;      // 1954

    float* pI2 = psm;                   // [T1] -> becomes S2 after down2
    float* pA2 = psm + T1;              // [T2]
    float* pI3 = pA2 + T2;              // [T2] -> becomes S3 after down3
    float* pA3 = pI3 + T2;              // [T3] -> scanned in place = S4

    ew_fused_kernel<<<(N + 4095) / 4096, 256>>>(
        sdf, grad, dirs, dt, ca, beta, palx, pI1, pI2, pA2, N, T1, T2);

    seg_kernel<<<(N + 255) / 256, 256>>>(ray_ids, N, n_rays, pseg);

    up_smem_kernel<<<(T3 + 255) / 256, 256>>>(pA2, T2, T3, pI3, pA3);

    midscan_down3_kernel<<<1, 256>>>(pA3, T3, pI3, T2);

    down2_kernel<<<(T1 + 255) / 256, 256>>>(pI3, pI2, T1);

    const int block = 256;
    const int wpb = block / 32;
    final_kernel<<<(n_rays + wpb - 1) / wpb, block>>>(
        palx, pI1, pI2, rgb, pseg, rgb_out, w_out, N, n_rays);
}

// round 16
// speedup vs baseline: 1.2041x; 1.2041x over previous
#include <cuda_runtime.h>

// VolumeRenderingNeuS — bit-faithful JAX/XLA:CPU emulation (ReduceWindowRewriter
// cumsum B=16, Cephes exp/log, strict RN) — 6-launch schedule:
//   K1 ew_fused : elementwise alpha/logx (float2) + I1 + I2 + A2
//   K2 seg      : scatter searchsorted(ray_ids) -> seg_start
//   K3 up3      : A2 (31250) -> I3 + A3 (1954)
//   K4 midscan  : scan A3 in one block (smem only) -> S4 in place
//   K5 down23   : full-grid elementwise: I2[j] = fl(fl(S4+I3) + I2[j]) -> S2
//   K6 final    : warp-per-ray; c = fl(fl(S2[t1-1]+I1[i]) - logx[i]);
//                 weights + per-ray rgb sums
// Every fl() op composes identically to the R10 passing kernel.

#define MAXN 8000000
#define MAXR ((1 << 18) + 2)
#define PAD(j) ((j) + ((j) >> 4))

__device__ float2 g_alx[MAXN];    // (alpha, logx) packed
__device__ float  g_I1[MAXN];
__device__ float  g_small[1200000];
__device__ int    g_seg[MAXR];

// ---- XLA:CPU Cephes/Eigen exp (no FMA) ----
__device__ __forceinline__ float cephes_expf(float input) {
    const float exp_hi = 88.3762626647950f;
    const float exp_lo = -88.3762626647949f;
    const float log2e  = 1.44269504088896341f;
    float xc = fminf(fmaxf(input, exp_lo), exp_hi);
    float fx = floorf(__fadd_rn(__fmul_rn(xc, log2e), 0.5f));
    float x = __fsub_rn(xc, __fmul_rn(0.693359375f, fx));
    x = __fsub_rn(x, __fmul_rn(-2.12194440e-4f, fx));
    float z = __fmul_rn(x, x);
    float y = __fadd_rn(__fmul_rn(x, 1.9875691500e-4f), 1.3981999507e-3f);
    y = __fadd_rn(__fmul_rn(y, x), 8.3334519073e-3f);
    y = __fadd_rn(__fmul_rn(y, x), 4.1665795894e-2f);
    y = __fadd_rn(__fmul_rn(y, x), 1.6666665459e-1f);
    y = __fadd_rn(__fmul_rn(y, x), 5.0000001201e-1f);
    y = __fadd_rn(__fmul_rn(y, z), x);
    y = __fadd_rn(1.0f, y);
    int n = (int)fx;
    return __fmul_rn(y, __int_as_float((n + 0x7f) << 23));
}

// ---- XLA:CPU Cephes/Eigen log (no FMA) ----
__device__ __forceinline__ float cephes_logf(float input) {
    const float sqrt_half = 0.707106781186547524f;
    int ix = __float_as_int(input);
    int emm0 = (int)(((unsigned)ix) >> 23) - 0x7e;
    float e = (float)emm0;
    float m = __int_as_float((ix & 0x807fffff) | 0x3f000000);
    bool mask = (m < sqrt_half);
    float tmp = mask ? m : 0.0f;
    float x = __fsub_rn(m, 1.0f);
    e = __fsub_rn(e, mask ? 1.0f : 0.0f);
    x = __fadd_rn(x, tmp);
    float z = __fmul_rn(x, x);
    float y = __fadd_rn(__fmul_rn(x, 7.0376836292e-2f), -1.1514610310e-1f);
    y = __fadd_rn(__fmul_rn(y, x), 1.1676998740e-1f);
    y = __fadd_rn(__fmul_rn(y, x), -1.2420140846e-1f);
    y = __fadd_rn(__fmul_rn(y, x), 1.4249322787e-1f);
    y = __fadd_rn(__fmul_rn(y, x), -1.6668057665e-1f);
    y = __fadd_rn(__fmul_rn(y, x), 2.0000714765e-1f);
    y = __fadd_rn(__fmul_rn(y, x), -2.4999993993e-1f);
    y = __fadd_rn(__fmul_rn(y, x), 3.3333331174e-1f);
    y = __fmul_rn(y, x);
    y = __fmul_rn(y, z);
    y = __fadd_rn(__fmul_rn(e, -2.12194440e-4f), y);
    y = __fsub_rn(y, __fmul_rn(0.5f, z));
    x = __fadd_rn(x, y);
    x = __fadd_rn(__fmul_rn(e, 0.693359375f), x);
    return x;
}

__device__ __forceinline__ float xla_sigmoid(float x) {
    return __fdiv_rn(1.0f, __fadd_rn(1.0f, cephes_expf(-x)));
}

// ---- K1: elementwise + level-1 scans (I1) + level-2 scans (I2,A2) ----
__global__ void __launch_bounds__(256)
ew_fused_kernel(const float* __restrict__ sdf, const float* __restrict__ grad,
                const float* __restrict__ dirs, const float* __restrict__ dt,
                const float* __restrict__ ca_p, const float* __restrict__ beta_p,
                float2* __restrict__ alx_out, float* __restrict__ I1,
                float* __restrict__ I2, float* __restrict__ A2,
                int N, int T1, int T2)
{
    __shared__ float sm[4352];
    __shared__ float smA[256];
    __shared__ float smI2[256];
    const int base = blockIdx.x * 4096;
    const float ca = ca_p[0];
    const float beta = beta_p[0];
    const float omca = __fsub_rn(1.0f, ca);

    #pragma unroll 1
    for (int k = 0; k < 16; k++) {
        int j = k * 256 + threadIdx.x;
        int i = base + j;
        float lx = 0.0f;
        if (i < N) {
            float m0 = __fmul_rn(dirs[3*i+0], grad[3*i+0]);
            float m1 = __fmul_rn(dirs[3*i+1], grad[3*i+1]);
            float m2 = __fmul_rn(dirs[3*i+2], grad[3*i+2]);
            float tc = __fadd_rn(__fadd_rn(m0, m1), m2);
            float ntc = -tc;
            float A = fmaxf(__fadd_rn(__fmul_rn(ntc, 0.5f), 0.5f), 0.0f);
            float Bv = fmaxf(ntc, 0.0f);
            float ic_pos = __fadd_rn(__fmul_rn(A, omca), __fmul_rn(Bv, ca));
            float m = __fmul_rn(ic_pos, dt[i]);
            float h = __fmul_rn(m, 0.5f);
            float s = sdf[i];
            float en = __fsub_rn(s, h);
            float ep = __fadd_rn(s, h);
            float pc = xla_sigmoid(__fmul_rn(ep, beta));
            float nc = xla_sigmoid(__fmul_rn(en, beta));
            float num = __fadd_rn(__fsub_rn(pc, nc), 1e-6f);
            float den = __fadd_rn(pc, 1e-6f);
            float a = fminf(fmaxf(__fdiv_rn(num, den), 0.0f), 1.0f);
            float om = __fadd_rn(__fsub_rn(1.0f, a), 1e-6f);
            lx = cephes_logf(om);
            alx_out[i] = make_float2(a, lx);
        }
        sm[PAD(j)] = lx;
    }
    __syncthreads();

    const int tg = blockIdx.x * 256 + threadIdx.x;   // global level-1 tile id
    {
        float a1 = 0.0f;
        if (tg < T1) {
            float acc = 0.0f;
            int jb = threadIdx.x * 16;
            #pragma unroll
            for (int c = 0; c < 16; c++) {
                int p = PAD(jb + c);
                acc = __fadd_rn(acc, sm[p]);
                sm[p] = acc;
            }
            a1 = acc;
        }
        smA[threadIdx.x] = a1;
    }
    __syncthreads();

    #pragma unroll 1
    for (int k = 0; k < 16; k++) {
        int j = k * 256 + threadIdx.x;
        int i = base + j;
        if (i < N) I1[i] = sm[PAD(j)];
    }

    if (threadIdx.x < 16) {
        int t2g = blockIdx.x * 16 + threadIdx.x;
        if (t2g < T2) {
            float acc = 0.0f;
            int jb = threadIdx.x * 16;
            #pragma unroll
            for (int c = 0; c < 16; c++) {
                acc = __fadd_rn(acc, smA[jb + c]);
                smI2[jb + c] = acc;
            }
            A2[t2g] = acc;
        }
    }
    __syncthreads();
    if (tg < T1) I2[tg] = smI2[threadIdx.x];
}

// ---- K2: scatter searchsorted -> seg_start ----
__global__ void __launch_bounds__(256)
seg_kernel(const int* __restrict__ ray_ids, int N, int n_rays,
           int* __restrict__ seg)
{
    int i = blockIdx.x * blockDim.x + threadIdx.x;
    if (i >= N) return;
    int cur = ray_ids[i];
    int prev = (i == 0) ? -1 : ray_ids[i - 1];
    for (int r = prev + 1; r <= cur; r++) seg[r] = i;
    if (i == N - 1)
        for (int r = cur + 1; r <= n_rays; r++) seg[r] = N;
}

// ---- K3: up level 3 (A2 -> I3, A3), smem-staged coalesced ----
__global__ void __launch_bounds__(256)
up_smem_kernel(const float* __restrict__ src, int n, int ntiles,
               float* __restrict__ inner, float* __restrict__ sums)
{
    __shared__ float sm[4352];
    const int base = blockIdx.x * 4096;
    #pragma unroll
    for (int k = 0; k < 16; k++) {
        int j = k * 256 + threadIdx.x;
        int g = base + j;
        sm[PAD(j)] = (g < n) ? src[g] : 0.0f;   // zero padding
    }
    __syncthreads();
    {
        int tg = blockIdx.x * 256 + threadIdx.x;
        if (tg < ntiles) {
            float acc = 0.0f;
            int jb = threadIdx.x * 16;
            #pragma unroll
            for (int c = 0; c < 16; c++) {
                int p = PAD(jb + c);
                acc = __fadd_rn(acc, sm[p]);
                sm[p] = acc;
            }
            sums[tg] = acc;
        }
    }
    __syncthreads();
    #pragma unroll
    for (int k = 0; k < 16; k++) {
        int j = k * 256 + threadIdx.x;
        int g = base + j;
        if (g < n) inner[g] = sm[PAD(j)];
    }
}

// ---- K4: pure single-block scan of A3 (smem only), in place -> S4 ----
__global__ void __launch_bounds__(256)
midscan_kernel(float* __restrict__ x, int n)
{
    __shared__ float sm[4400];
    int m[8], off[8];
    int L = 0; m[0] = n; off[0] = 0;
    while (m[L] > 16) {
        m[L+1] = (m[L] + 15) / 16;
        off[L+1] = off[L] + m[L];
        L++;
    }
    for (int i = threadIdx.x; i < n; i += blockDim.x) sm[i] = x[i];
    __syncthreads();

    for (int l = 0; l < L; l++) {
        for (int t = threadIdx.x; t < m[l+1]; t += blockDim.x) {
            float acc = 0.0f;
            int b = off[l] + t * 16;
            for (int c = 0; c < 16; c++) {
                int j = t * 16 + c;
                float v = (j < m[l]) ? sm[b + c] : 0.0f;
                acc = __fadd_rn(acc, v);
                if (j < m[l]) sm[b + c] = acc;
            }
            sm[off[l+1] + t] = acc;
        }
        __syncthreads();
    }
    if (threadIdx.x == 0) {
        float acc = 0.0f;
        for (int i = 0; i < m[L]; i++) {
            acc = __fadd_rn(acc, sm[off[L] + i]);
            sm[off[L] + i] = acc;
        }
    }
    __syncthreads();
    for (int l = L - 1; l >= 0; l--) {
        for (int t = threadIdx.x; t < m[l+1]; t += blockDim.x) {
            if (t == 0) continue;
            float o = sm[off[l+1] + t - 1];
            int b = off[l] + t * 16;
            for (int c = 0; c < 16; c++) {
                int j = t * 16 + c;
                if (j < m[l]) sm[b + c] = __fadd_rn(o, sm[b + c]);
            }
        }
        __syncthreads();
    }
    for (int i = threadIdx.x; i < n; i += blockDim.x) x[i] = sm[i];
}

// ---- K5: fused down3+down2, full grid, elementwise over level-2 ----
// S3[j3] = fl(S4[j3/16 - 1] + I3[j3])  (only when j3/16 >= 1)
// S2[j]  = fl(S3[j/16 - 1] + I2[j])    (only when j/16  >= 1)
// Composition identical to the separate down3/down2 passes.
__global__ void __launch_bounds__(256)
down23_kernel(const float* __restrict__ S4, const float* __restrict__ I3,
              float* __restrict__ I2, int n)
{
    int j = blockIdx.x * blockDim.x + threadIdx.x;
    if (j >= n) return;
    int t = j >> 4;
    if (t == 0) return;
    int j3 = t - 1;
    float s3 = I3[j3];
    int t3 = j3 >> 4;
    if (t3) s3 = __fadd_rn(S4[t3 - 1], s3);
    I2[j] = __fadd_rn(s3, I2[j]);
}

// ---- K6: warp-per-ray weights + rgb segment sums (2-load cexcl) ----
__global__ void __launch_bounds__(256)
final_kernel(const float2* __restrict__ alx, const float* __restrict__ I1,
             const float* __restrict__ S2, const float* __restrict__ rgb,
             const int* __restrict__ seg,
             float* __restrict__ rgb_out, float* __restrict__ w_out,
             int N, int n_rays)
{
    const int r = (blockIdx.x * (blockDim.x >> 5)) + (threadIdx.x >> 5);
    const int lane = threadIdx.x & 31;
    if (r >= n_rays) return;

    const int start = seg[r];
    const int end   = seg[r + 1];

    float base = 0.0f;
    if (start < end) {
        float2 al0 = alx[start];
        int t = start >> 4;
        float s = I1[start];
        if (t) s = __fadd_rn(S2[t - 1], s);
        base = __fsub_rn(s, al0.y);
    }

    float ax = 0.0f, ay = 0.0f, az = 0.0f;
    for (int i = start + lane; i < end; i += 32) {
        float2 al = alx[i];
        int t = i >> 4;
        float s = I1[i];
        if (t) s = __fadd_rn(S2[t - 1], s);
        float c = __fsub_rn(s, al.y);
        float T = cephes_expf(__fsub_rn(c, base));
        float w = __fmul_rn(al.x, T);
        w_out[i] = w;
        ax = __fadd_rn(ax, __fmul_rn(w, rgb[3*i+0]));
        ay = __fadd_rn(ay, __fmul_rn(w, rgb[3*i+1]));
        az = __fadd_rn(az, __fmul_rn(w, rgb[3*i+2]));
    }
    #pragma unroll
    for (int o = 16; o; o >>= 1) {
        ax = __fadd_rn(ax, __shfl_xor_sync(0xffffffffu, ax, o));
        ay = __fadd_rn(ay, __shfl_xor_sync(0xffffffffu, ay, o));
        az = __fadd_rn(az, __shfl_xor_sync(0xffffffffu, az, o));
    }
    if (lane == 0) {
        rgb_out[3*r+0] = ax;
        rgb_out[3*r+1] = ay;
        rgb_out[3*r+2] = az;
    }
}

extern "C" void kernel_launch(void* const* d_in, const int* in_sizes, int n_in,
                              void* d_out, int out_size)
{
    const float* sdf     = (const float*)d_in[0];
    const float* grad    = (const float*)d_in[1];
    const float* dirs    = (const float*)d_in[2];
    const float* dt      = (const float*)d_in[3];
    const float* rgb     = (const float*)d_in[4];
    const float* ca      = (const float*)d_in[5];
    const float* beta    = (const float*)d_in[6];
    const int*   ray_ids = (const int*)d_in[7];

    const int N      = in_sizes[0];
    const int n_rays = (out_size - N) / 3;
    float* out     = (float*)d_out;
    float* rgb_out = out;
    float* w_out   = out + 3 * n_rays;

    float2* palx;
    float *pI1, *psm;
    int *pseg;
    cudaGetSymbolAddress((void**)&palx, g_alx);
    cudaGetSymbolAddress((void**)&pI1,  g_I1);
    cudaGetSymbolAddress((void**)&psm,  g_small);
    cudaGetSymbolAddress((void**)&pseg, g_seg);

    const int T1 = (N + 15) / 16;       // 500000
    const int T2 = (T1 + 15) / 16;      // 31250
    const int T3 = (T2 + 15) / 16;      // 1954

    float* pI2 = psm;                   // [T1] -> becomes S2 after down23
    float* pA2 = psm + T1;              // [T2]
    float* pI3 = pA2 + T2;              // [T2]
    float* pA3 = pI3 + T2;              // [T3] -> scanned in place = S4

    ew_fused_kernel<<<(N + 4095) / 4096, 256>>>(
        sdf, grad, dirs, dt, ca, beta, palx, pI1, pI2, pA2, N, T1, T2);

    seg_kernel<<<(N + 255) / 256, 256>>>(ray_ids, N, n_rays, pseg);

    up_smem_kernel<<<(T3 + 255) / 256, 256>>>(pA2, T2, T3, pI3, pA3);

    midscan_kernel<<<1, 256>>>(pA3, T3);

    down23_kernel<<<(T1 + 255) / 256, 256>>>(pA3, pI3, pI2, T1);

    const int block = 256;
    const int wpb = block / 32;
    final_kernel<<<(n_rays + wpb - 1) / wpb, block>>>(
        palx, pI1, pI2, rgb, pseg, rgb_out, w_out, N, n_rays);
}

// round 17
// speedup vs baseline: 1.4567x; 1.2097x over previous
#include <cuda_runtime.h>

// VolumeRenderingNeuS — bit-faithful JAX/XLA:CPU emulation (ReduceWindowRewriter
// cumsum B=16, Cephes exp/log, strict RN) — 5-launch schedule:
//   K1 ew_fused : elementwise alpha/logx (float2) + I1 + I2 + A2 + seg scatter
//   K2 up3      : A2 (31250) -> I3 + A3 (1954)
//   K3 midscan  : scan A3 in one block (padded smem, conflict-free) -> S4
//   K4 down23   : full-grid elementwise: I2[j] = fl(fl(S4+I3) + I2[j]) -> S2
//   K5 final    : warp-per-ray; c = fl(fl(S2[t1-1]+I1[i]) - logx[i]);
//                 weights + per-ray rgb sums
// Every fl() op composes identically to the R10/R16 passing kernels.

#define MAXN 8000000
#define MAXR ((1 << 18) + 2)
#define PAD(j) ((j) + ((j) >> 4))

__device__ float2 g_alx[MAXN];    // (alpha, logx) packed
__device__ float  g_I1[MAXN];
__device__ float  g_small[1200000];
__device__ int    g_seg[MAXR];

// ---- XLA:CPU Cephes/Eigen exp (no FMA) ----
__device__ __forceinline__ float cephes_expf(float input) {
    const float exp_hi = 88.3762626647950f;
    const float exp_lo = -88.3762626647949f;
    const float log2e  = 1.44269504088896341f;
    float xc = fminf(fmaxf(input, exp_lo), exp_hi);
    float fx = floorf(__fadd_rn(__fmul_rn(xc, log2e), 0.5f));
    float x = __fsub_rn(xc, __fmul_rn(0.693359375f, fx));
    x = __fsub_rn(x, __fmul_rn(-2.12194440e-4f, fx));
    float z = __fmul_rn(x, x);
    float y = __fadd_rn(__fmul_rn(x, 1.9875691500e-4f), 1.3981999507e-3f);
    y = __fadd_rn(__fmul_rn(y, x), 8.3334519073e-3f);
    y = __fadd_rn(__fmul_rn(y, x), 4.1665795894e-2f);
    y = __fadd_rn(__fmul_rn(y, x), 1.6666665459e-1f);
    y = __fadd_rn(__fmul_rn(y, x), 5.0000001201e-1f);
    y = __fadd_rn(__fmul_rn(y, z), x);
    y = __fadd_rn(1.0f, y);
    int n = (int)fx;
    return __fmul_rn(y, __int_as_float((n + 0x7f) << 23));
}

// ---- XLA:CPU Cephes/Eigen log (no FMA) ----
__device__ __forceinline__ float cephes_logf(float input) {
    const float sqrt_half = 0.707106781186547524f;
    int ix = __float_as_int(input);
    int emm0 = (int)(((unsigned)ix) >> 23) - 0x7e;
    float e = (float)emm0;
    float m = __int_as_float((ix & 0x807fffff) | 0x3f000000);
    bool mask = (m < sqrt_half);
    float tmp = mask ? m : 0.0f;
    float x = __fsub_rn(m, 1.0f);
    e = __fsub_rn(e, mask ? 1.0f : 0.0f);
    x = __fadd_rn(x, tmp);
    float z = __fmul_rn(x, x);
    float y = __fadd_rn(__fmul_rn(x, 7.0376836292e-2f), -1.1514610310e-1f);
    y = __fadd_rn(__fmul_rn(y, x), 1.1676998740e-1f);
    y = __fadd_rn(__fmul_rn(y, x), -1.2420140846e-1f);
    y = __fadd_rn(__fmul_rn(y, x), 1.4249322787e-1f);
    y = __fadd_rn(__fmul_rn(y, x), -1.6668057665e-1f);
    y = __fadd_rn(__fmul_rn(y, x), 2.0000714765e-1f);
    y = __fadd_rn(__fmul_rn(y, x), -2.4999993993e-1f);
    y = __fadd_rn(__fmul_rn(y, x), 3.3333331174e-1f);
    y = __fmul_rn(y, x);
    y = __fmul_rn(y, z);
    y = __fadd_rn(__fmul_rn(e, -2.12194440e-4f), y);
    y = __fsub_rn(y, __fmul_rn(0.5f, z));
    x = __fadd_rn(x, y);
    x = __fadd_rn(__fmul_rn(e, 0.693359375f), x);
    return x;
}

__device__ __forceinline__ float xla_sigmoid(float x) {
    return __fdiv_rn(1.0f, __fadd_rn(1.0f, cephes_expf(-x)));
}

// ---- K1: elementwise + level-1/level-2 scans + seg scatter ----
__global__ void __launch_bounds__(256)
ew_fused_kernel(const float* __restrict__ sdf, const float* __restrict__ grad,
                const float* __restrict__ dirs, const float* __restrict__ dt,
                const float* __restrict__ ca_p, const float* __restrict__ beta_p,
                const int* __restrict__ ray_ids, int* __restrict__ seg,
                float2* __restrict__ alx_out, float* __restrict__ I1,
                float* __restrict__ I2, float* __restrict__ A2,
                int N, int T1, int T2, int n_rays)
{
    __shared__ float sm[4352];
    __shared__ float smA[256];
    __shared__ float smI2[256];
    const int base = blockIdx.x * 4096;
    const float ca = ca_p[0];
    const float beta = beta_p[0];
    const float omca = __fsub_rn(1.0f, ca);

    #pragma unroll 1
    for (int k = 0; k < 16; k++) {
        int j = k * 256 + threadIdx.x;
        int i = base + j;
        float lx = 0.0f;
        if (i < N) {
            // seg scatter: transitions of sorted ray_ids
            int cur  = ray_ids[i];
            int prev = (i == 0) ? -1 : ray_ids[i - 1];
            for (int r = prev + 1; r <= cur; r++) seg[r] = i;
            if (i == N - 1)
                for (int r = cur + 1; r <= n_rays; r++) seg[r] = N;

            float m0 = __fmul_rn(dirs[3*i+0], grad[3*i+0]);
            float m1 = __fmul_rn(dirs[3*i+1], grad[3*i+1]);
            float m2 = __fmul_rn(dirs[3*i+2], grad[3*i+2]);
            float tc = __fadd_rn(__fadd_rn(m0, m1), m2);
            float ntc = -tc;
            float A = fmaxf(__fadd_rn(__fmul_rn(ntc, 0.5f), 0.5f), 0.0f);
            float Bv = fmaxf(ntc, 0.0f);
            float ic_pos = __fadd_rn(__fmul_rn(A, omca), __fmul_rn(Bv, ca));
            float m = __fmul_rn(ic_pos, dt[i]);
            float h = __fmul_rn(m, 0.5f);
            float s = sdf[i];
            float en = __fsub_rn(s, h);
            float ep = __fadd_rn(s, h);
            float pc = xla_sigmoid(__fmul_rn(ep, beta));
            float nc = xla_sigmoid(__fmul_rn(en, beta));
            float num = __fadd_rn(__fsub_rn(pc, nc), 1e-6f);
            float den = __fadd_rn(pc, 1e-6f);
            float a = fminf(fmaxf(__fdiv_rn(num, den), 0.0f), 1.0f);
            float om = __fadd_rn(__fsub_rn(1.0f, a), 1e-6f);
            lx = cephes_logf(om);
            alx_out[i] = make_float2(a, lx);
        }
        sm[PAD(j)] = lx;
    }
    __syncthreads();

    const int tg = blockIdx.x * 256 + threadIdx.x;   // global level-1 tile id
    {
        float a1 = 0.0f;
        if (tg < T1) {
            float acc = 0.0f;
            int jb = threadIdx.x * 16;
            #pragma unroll
            for (int c = 0; c < 16; c++) {
                int p = PAD(jb + c);
                acc = __fadd_rn(acc, sm[p]);
                sm[p] = acc;
            }
            a1 = acc;
        }
        smA[threadIdx.x] = a1;
    }
    __syncthreads();

    #pragma unroll 1
    for (int k = 0; k < 16; k++) {
        int j = k * 256 + threadIdx.x;
        int i = base + j;
        if (i < N) I1[i] = sm[PAD(j)];
    }

    if (threadIdx.x < 16) {
        int t2g = blockIdx.x * 16 + threadIdx.x;
        if (t2g < T2) {
            float acc = 0.0f;
            int jb = threadIdx.x * 16;
            #pragma unroll
            for (int c = 0; c < 16; c++) {
                acc = __fadd_rn(acc, smA[jb + c]);
                smI2[jb + c] = acc;
            }
            A2[t2g] = acc;
        }
    }
    __syncthreads();
    if (tg < T1) I2[tg] = smI2[threadIdx.x];
}

// ---- K2: up level 3 (A2 -> I3, A3), smem-staged coalesced ----
__global__ void __launch_bounds__(256)
up_smem_kernel(const float* __restrict__ src, int n, int ntiles,
               float* __restrict__ inner, float* __restrict__ sums)
{
    __shared__ float sm[4352];
    const int base = blockIdx.x * 4096;
    #pragma unroll
    for (int k = 0; k < 16; k++) {
        int j = k * 256 + threadIdx.x;
        int g = base + j;
        sm[PAD(j)] = (g < n) ? src[g] : 0.0f;   // zero padding
    }
    __syncthreads();
    {
        int tg = blockIdx.x * 256 + threadIdx.x;
        if (tg < ntiles) {
            float acc = 0.0f;
            int jb = threadIdx.x * 16;
            #pragma unroll
            for (int c = 0; c < 16; c++) {
                int p = PAD(jb + c);
                acc = __fadd_rn(acc, sm[p]);
                sm[p] = acc;
            }
            sums[tg] = acc;
        }
    }
    __syncthreads();
    #pragma unroll
    for (int k = 0; k < 16; k++) {
        int j = k * 256 + threadIdx.x;
        int g = base + j;
        if (g < n) inner[g] = sm[PAD(j)];
    }
}

// ---- K3: single-block scan of A3 (padded smem, conflict-free) -> S4 ----
__global__ void __launch_bounds__(256)
midscan_kernel(float* __restrict__ x, int n)
{
    __shared__ float sm[2400];   // PAD(2085) = 2215 max for n <= 1954
    int m[8], off[8];
    int L = 0; m[0] = n; off[0] = 0;
    while (m[L] > 16) {
        m[L+1] = (m[L] + 15) / 16;
        off[L+1] = off[L] + m[L];
        L++;
    }
    for (int i = threadIdx.x; i < n; i += blockDim.x) sm[PAD(i)] = x[i];
    __syncthreads();

    for (int l = 0; l < L; l++) {
        for (int t = threadIdx.x; t < m[l+1]; t += blockDim.x) {
            float acc = 0.0f;
            int b = off[l] + t * 16;
            for (int c = 0; c < 16; c++) {
                int j = t * 16 + c;
                float v = (j < m[l]) ? sm[PAD(b + c)] : 0.0f;
                acc = __fadd_rn(acc, v);
                if (j < m[l]) sm[PAD(b + c)] = acc;
            }
            sm[PAD(off[l+1] + t)] = acc;
        }
        __syncthreads();
    }
    if (threadIdx.x == 0) {
        float acc = 0.0f;
        for (int i = 0; i < m[L]; i++) {
            acc = __fadd_rn(acc, sm[PAD(off[L] + i)]);
            sm[PAD(off[L] + i)] = acc;
        }
    }
    __syncthreads();
    for (int l = L - 1; l >= 0; l--) {
        for (int t = threadIdx.x; t < m[l+1]; t += blockDim.x) {
            if (t == 0) continue;
            float o = sm[PAD(off[l+1] + t - 1)];
            int b = off[l] + t * 16;
            for (int c = 0; c < 16; c++) {
                int j = t * 16 + c;
                if (j < m[l]) sm[PAD(b + c)] = __fadd_rn(o, sm[PAD(b + c)]);
            }
        }
        __syncthreads();
    }
    for (int i = threadIdx.x; i < n; i += blockDim.x) x[i] = sm[PAD(i)];
}

// ---- K4: fused down3+down2, full grid, elementwise over level-2 ----
__global__ void __launch_bounds__(256)
down23_kernel(const float* __restrict__ S4, const float* __restrict__ I3,
              float* __restrict__ I2, int n)
{
    int j = blockIdx.x * blockDim.x + threadIdx.x;
    if (j >= n) return;
    int t = j >> 4;
    if (t == 0) return;
    int j3 = t - 1;
    float s3 = I3[j3];
    int t3 = j3 >> 4;
    if (t3) s3 = __fadd_rn(S4[t3 - 1], s3);
    I2[j] = __fadd_rn(s3, I2[j]);
}

// ---- K5: warp-per-ray weights + rgb segment sums (2-load cexcl) ----
__global__ void __launch_bounds__(256)
final_kernel(const float2* __restrict__ alx, const float* __restrict__ I1,
             const float* __restrict__ S2, const float* __restrict__ rgb,
             const int* __restrict__ seg,
             float* __restrict__ rgb_out, float* __restrict__ w_out,
             int N, int n_rays)
{
    const int r = (blockIdx.x * (blockDim.x >> 5)) + (threadIdx.x >> 5);
    const int lane = threadIdx.x & 31;
    if (r >= n_rays) return;

    const int start = seg[r];
    const int end   = seg[r + 1];

    float base = 0.0f;
    if (start < end) {
        float2 al0 = alx[start];
        int t = start >> 4;
        float s = I1[start];
        if (t) s = __fadd_rn(S2[t - 1], s);
        base = __fsub_rn(s, al0.y);
    }

    float ax = 0.0f, ay = 0.0f, az = 0.0f;
    for (int i = start + lane; i < end; i += 32) {
        float2 al = alx[i];
        int t = i >> 4;
        float s = I1[i];
        if (t) s = __fadd_rn(S2[t - 1], s);
        float c = __fsub_rn(s, al.y);
        float T = cephes_expf(__fsub_rn(c, base));
        float w = __fmul_rn(al.x, T);
        w_out[i] = w;
        ax = __fadd_rn(ax, __fmul_rn(w, rgb[3*i+0]));
        ay = __fadd_rn(ay, __fmul_rn(w, rgb[3*i+1]));
        az = __fadd_rn(az, __fmul_rn(w, rgb[3*i+2]));
    }
    #pragma unroll
    for (int o = 16; o; o >>= 1) {
        ax = __fadd_rn(ax, __shfl_xor_sync(0xffffffffu, ax, o));
        ay = __fadd_rn(ay, __shfl_xor_sync(0xffffffffu, ay, o));
        az = __fadd_rn(az, __shfl_xor_sync(0xffffffffu, az, o));
    }
    if (lane == 0) {
        rgb_out[3*r+0] = ax;
        rgb_out[3*r+1] = ay;
        rgb_out[3*r+2] = az;
    }
}

extern "C" void kernel_launch(void* const* d_in, const int* in_sizes, int n_in,
                              void* d_out, int out_size)
{
    const float* sdf     = (const float*)d_in[0];
    const float* grad    = (const float*)d_in[1];
    const float* dirs    = (const float*)d_in[2];
    const float* dt      = (const float*)d_in[3];
    const float* rgb     = (const float*)d_in[4];
    const float* ca      = (const float*)d_in[5];
    const float* beta    = (const float*)d_in[6];
    const int*   ray_ids = (const int*)d_in[7];

    const int N      = in_sizes[0];
    const int n_rays = (out_size - N) / 3;
    float* out     = (float*)d_out;
    float* rgb_out = out;
    float* w_out   = out + 3 * n_rays;

    float2* palx;
    float *pI1, *psm;
    int *pseg;
    cudaGetSymbolAddress((void**)&palx, g_alx);
    cudaGetSymbolAddress((void**)&pI1,  g_I1);
    cudaGetSymbolAddress((void**)&psm,  g_small);
    cudaGetSymbolAddress((void**)&pseg, g_seg);

    const int T1 = (N + 15) / 16;       // 500000
    const int T2 = (T1 + 15) / 16;      // 31250
    const int T3 = (T2 + 15) / 16;      // 1954

    float* pI2 = psm;                   // [T1] -> becomes S2 after down23
    float* pA2 = psm + T1;              // [T2]
    float* pI3 = pA2 + T2;              // [T2]
    float* pA3 = pI3 + T2;              // [T3] -> scanned in place = S4

    ew_fused_kernel<<<(N + 4095) / 4096, 256>>>(
        sdf, grad, dirs, dt, ca, beta, ray_ids, pseg,
        palx, pI1, pI2, pA2, N, T1, T2, n_rays);

    up_smem_kernel<<<(T3 + 255) / 256, 256>>>(pA2, T2, T3, pI3, pA3);

    midscan_kernel<<<1, 256>>>(pA3, T3);

    down23_kernel<<<(T1 + 255) / 256, 256>>>(pA3, pI3, pI2, T1);

    const int block = 256;
    const int wpb = block / 32;
    final_kernel<<<(n_rays + wpb - 1) / wpb, block>>>(
        palx, pI1, pI2, rgb, pseg, rgb_out, w_out, N, n_rays);
}